// round 16
// baseline (speedup 1.0000x reference)
#include <cuda_runtime.h>
#include <cuda_bf16.h>
#include <cstdint>

// WindowAttention3D: B_=4096, N=98 tok, C=96, H=3 heads, hd=32.
// R16: R15 + register-hoisted operand fragments in attention:
// S holds Q-frags across n-tiles; PV holds per-nt accumulators with
// ks-outer transient P-frags. Same math order -> identical numerics.

#define N_TOK 98
#define C_DIM 96
#define NHEAD 3
#define NTHREADS 384

typedef unsigned long long u64;

// ---------------- helpers ----------------
__device__ __forceinline__ uint32_t smem_u32(const void* p) {
    uint32_t a;
    asm("{ .reg .u64 t; cvta.to.shared.u64 t, %1; cvt.u32.u64 %0, t; }"
        : "=r"(a) : "l"(p));
    return a;
}
__device__ __forceinline__ void ldsm4(uint32_t& r0, uint32_t& r1,
                                      uint32_t& r2, uint32_t& r3, uint32_t a) {
    asm volatile("ldmatrix.sync.aligned.m8n8.x4.shared.b16 {%0,%1,%2,%3}, [%4];"
                 : "=r"(r0), "=r"(r1), "=r"(r2), "=r"(r3) : "r"(a));
}
__device__ __forceinline__ void ldsm2(uint32_t& r0, uint32_t& r1, uint32_t a) {
    asm volatile("ldmatrix.sync.aligned.m8n8.x2.shared.b16 {%0,%1}, [%2];"
                 : "=r"(r0), "=r"(r1) : "r"(a));
}
__device__ __forceinline__ void ldsm2t(uint32_t& r0, uint32_t& r1, uint32_t a) {
    asm volatile("ldmatrix.sync.aligned.m8n8.x2.trans.shared.b16 {%0,%1}, [%2];"
                 : "=r"(r0), "=r"(r1) : "r"(a));
}
__device__ __forceinline__ void mma16816(float* c, const uint32_t* a,
                                         const uint32_t* b) {
    asm volatile("mma.sync.aligned.m16n8k16.row.col.f32.bf16.bf16.f32 "
                 "{%0,%1,%2,%3}, {%4,%5,%6,%7}, {%8,%9}, {%0,%1,%2,%3};"
                 : "+f"(c[0]), "+f"(c[1]), "+f"(c[2]), "+f"(c[3])
                 : "r"(a[0]), "r"(a[1]), "r"(a[2]), "r"(a[3]),
                   "r"(b[0]), "r"(b[1]));
}
__device__ __forceinline__ void split_bf16(float f, __nv_bfloat16& h, __nv_bfloat16& l) {
    h = __float2bfloat16(f);
    l = __float2bfloat16(f - __bfloat162float(h));
}
__device__ __forceinline__ void st_bf162(char* p, __nv_bfloat16 a, __nv_bfloat16 b) {
    __nv_bfloat162 t; t.x = a; t.y = b;
    *reinterpret_cast<__nv_bfloat162*>(p) = t;
}

// swizzled byte offsets (c = bf16 element column)
__device__ __forceinline__ int swA(int r, int c) {          // A: 192B rows
    return ((r * 96 + c) * 2) ^ (((r >> 1) & 3) << 4);
}
__device__ __forceinline__ int sw_qk(int r, int c) {        // q/k: 64B rows
    return (r * 64 + c * 2) ^ (((r >> 1) & 3) << 4);
}
__device__ __forceinline__ int sw_p(int r, int c) {         // P: 224B rows
    return (r * 224 + c * 2) ^ (((r >> 2) & 1) << 4);
}
// V: [m][40] bf16, 80B rows, no xor needed.

// ---------------- smem map (bytes) ----------------
constexpr int SM_A_HI = 0;                     // 112 x 192B
constexpr int SM_A_LO = 21504;
constexpr int SM_QH   = 43008;                 // + g*7168 (112 x 64B)
constexpr int SM_QL   = 64512;
constexpr int SM_KH   = 86016;                 // + g*6656 (104 x 64B)
constexpr int SM_KL   = 105984;
constexpr int SM_VH   = 125952;                // + g*8960 (112 x 80B)
constexpr int SM_VL   = 152832;
constexpr int SM_P    = 179712;                // + g*14336 (hi 7168 | lo 7168)
constexpr int SM_LSUM = 222720;                // 96 floats
constexpr int SM_OST  = SM_QH;                 // f32 out staging 98x100
constexpr int SMEM_BYTES = 223104;

// ---------------- device globals ----------------
__device__ float g_bias[NHEAD * N_TOK * N_TOK];        // [h][r][m]
__device__ __nv_bfloat16 g_wq_hi[288 * 96];            // row-major [n][k]
__device__ __nv_bfloat16 g_wq_lo[288 * 96];
__device__ __nv_bfloat16 g_wp_hi[96 * 96];
__device__ __nv_bfloat16 g_wp_lo[96 * 96];

__global__ void prep_all_kernel(const float* __restrict__ qkv_w,
                                const float* __restrict__ proj_w,
                                const float* __restrict__ table,
                                const int* __restrict__ rel) {
    int idx = blockIdx.x * blockDim.x + threadIdx.x;
    const int QE = 288 * 96, PE = 96 * 96;
    if (idx < QE) {
        float v = qkv_w[idx];
        __nv_bfloat16 hi, lo; split_bf16(v, hi, lo);
        g_wq_hi[idx] = hi;  g_wq_lo[idx] = lo;
    } else if (idx < QE + PE) {
        float v = proj_w[idx - QE];
        __nv_bfloat16 hi, lo; split_bf16(v, hi, lo);
        g_wp_hi[idx - QE] = hi;  g_wp_lo[idx - QE] = lo;
    } else if (idx < QE + PE + NHEAD * N_TOK * N_TOK) {
        int j = idx - QE - PE;
        int h   = j / (N_TOK * N_TOK);
        int rem = j - h * (N_TOK * N_TOK);
        int r   = rem / N_TOK;
        int m   = rem - r * N_TOK;
        g_bias[j] = table[rel[r * N_TOK + m] * NHEAD + h];
    }
}

// ---------------- main kernel ----------------
__global__ __launch_bounds__(NTHREADS, 1)
void win_attn_mma(const float* __restrict__ x,
                  const float* __restrict__ qkv_b,
                  const float* __restrict__ proj_b,
                  float* __restrict__ out) {
    extern __shared__ char smc[];
    const uint32_t sb = smem_u32(smc);
    const int tid  = threadIdx.x;
    const int wid  = tid >> 5;
    const int lane = tid & 31;
    const long base = (long)blockIdx.x * (N_TOK * C_DIM);

    const int arow_l = (lane & 7) + ((lane >> 3) & 1) * 8;
    const int acol_l = (lane >> 4) * 8;
    const int l15    = lane & 15;
    const int nrow_l = lane >> 2;          // B-frag n / C-frag row (0..7)
    const int kk_l   = (lane & 3) * 2;     // B-frag k / C-frag col pair

    // ---- zero V region; P pad cols; split x -> A hi/lo; ones col ----
    {
        uint4 z = {0, 0, 0, 0};
        uint4* vz = reinterpret_cast<uint4*>(smc + SM_VH);
        for (int i = tid; i < 2 * 3 * 8960 / 16; i += NTHREADS) vz[i] = z;
        for (int i = tid; i < 192; i += NTHREADS) {
            int g = i / 64, rb = i - g * 64;
            int bsel = rb >> 5, r = rb & 31;
            *reinterpret_cast<uint4*>(smc + SM_P + g * 14336 + bsel * 7168
                                      + sw_p(r, 104)) = z;
        }
    }
    for (int i = tid; i < N_TOK * (C_DIM / 2); i += NTHREADS) {
        int row = i / (C_DIM / 2), cp = i - row * (C_DIM / 2);
        float2 v = *reinterpret_cast<const float2*>(x + base + row * C_DIM + cp * 2);
        __nv_bfloat16 h0, l0, h1, l1;
        split_bf16(v.x, h0, l0);  split_bf16(v.y, h1, l1);
        int off = swA(row, cp * 2);
        st_bf162(smc + SM_A_HI + off, h0, h1);
        st_bf162(smc + SM_A_LO + off, l0, l1);
    }
    __syncthreads();
    for (int i = tid; i < NHEAD * N_TOK; i += NTHREADS) {
        int g = i / N_TOK, m = i - g * N_TOK;
        *reinterpret_cast<__nv_bfloat16*>(smc + SM_VH + g * 8960 + (m * 40 + 32) * 2) =
            __float2bfloat16(1.0f);
    }

    // ---- Phase B: QKV GEMM, 3 passes; B-frags direct from gmem ----
    const float scale = 0.17677669529663687f;   // 1/sqrt(32)
    const int ng = wid % 6;
    const int mg = wid / 6;
    const int m_begin = mg * 4;
    const int m_end   = (mg == 0) ? 4 : 7;

    #pragma unroll 1
    for (int s = 0; s < 3; s++) {
        uint32_t bh[2][6][2], bl[2][6][2];
        #pragma unroll
        for (int nt = 0; nt < 2; nt++) {
            int n = (2 * ng + nt) * 8 + nrow_l;
            const __nv_bfloat16* WH = g_wq_hi + (s * 96 + n) * 96;
            const __nv_bfloat16* WL = g_wq_lo + (s * 96 + n) * 96;
            #pragma unroll
            for (int ks = 0; ks < 6; ks++) {
                bh[nt][ks][0] = __ldg(reinterpret_cast<const uint32_t*>(WH + ks * 16 + kk_l));
                bh[nt][ks][1] = __ldg(reinterpret_cast<const uint32_t*>(WH + ks * 16 + kk_l + 8));
                bl[nt][ks][0] = __ldg(reinterpret_cast<const uint32_t*>(WL + ks * 16 + kk_l));
                bl[nt][ks][1] = __ldg(reinterpret_cast<const uint32_t*>(WL + ks * 16 + kk_l + 8));
            }
        }
        for (int mt = m_begin; mt < m_end; mt++) {
            float acc[2][4] = {{0.f, 0.f, 0.f, 0.f}, {0.f, 0.f, 0.f, 0.f}};
            #pragma unroll
            for (int ksi = 0; ksi < 6; ksi++) {
                uint32_t offA = (uint32_t)swA(mt * 16 + arow_l, ksi * 16 + acol_l);
                uint32_t ah[4], al[4];
                ldsm4(ah[0], ah[1], ah[2], ah[3], sb + SM_A_HI + offA);
                ldsm4(al[0], al[1], al[2], al[3], sb + SM_A_LO + offA);
                #pragma unroll
                for (int nt = 0; nt < 2; nt++) {
                    mma16816(acc[nt], ah, bh[nt][ksi]);
                    mma16816(acc[nt], ah, bl[nt][ksi]);
                    mma16816(acc[nt], al, bh[nt][ksi]);
                }
            }
            #pragma unroll
            for (int nt = 0; nt < 2; nt++) {
                int col = (2 * ng + nt) * 8 + kk_l;
                int hh = col >> 5, dd = col & 31;
                float b0 = __ldg(&qkv_b[s * C_DIM + col]);
                float b1 = __ldg(&qkv_b[s * C_DIM + col + 1]);
                float mul = (s == 0) ? scale : 1.0f;
                #pragma unroll
                for (int half = 0; half < 2; half++) {
                    int r = mt * 16 + nrow_l + half * 8;
                    if (r >= N_TOK) continue;
                    float f0 = (acc[nt][2 * half + 0] + b0) * mul;
                    float f1 = (acc[nt][2 * half + 1] + b1) * mul;
                    __nv_bfloat16 h0, l0, h1, l1;
                    split_bf16(f0, h0, l0);  split_bf16(f1, h1, l1);
                    if (s == 0) {
                        int o = sw_qk(r, dd);
                        st_bf162(smc + SM_QH + hh * 7168 + o, h0, h1);
                        st_bf162(smc + SM_QL + hh * 7168 + o, l0, l1);
                    } else if (s == 1) {
                        int o = sw_qk(r, dd);
                        st_bf162(smc + SM_KH + hh * 6656 + o, h0, h1);
                        st_bf162(smc + SM_KL + hh * 6656 + o, l0, l1);
                    } else {
                        int o = (r * 40 + dd) * 2;
                        st_bf162(smc + SM_VH + hh * 8960 + o, h0, h1);
                        st_bf162(smc + SM_VL + hh * 8960 + o, l0, l1);
                    }
                }
            }
        }
    }
    __syncthreads();

    // ---- Attention: 4 warps per head, named barriers, 4 row-groups ----
    {
        const int g    = wid >> 2;
        const int subw = wid & 3;
        const uint32_t qhB = sb + SM_QH + g * 7168;
        const uint32_t qlB = sb + SM_QL + g * 7168;
        const uint32_t khB = sb + SM_KH + g * 6656;
        const uint32_t klB = sb + SM_KL + g * 6656;
        const uint32_t vhB = sb + SM_VH + g * 8960;
        const uint32_t vlB = sb + SM_VL + g * 8960;
        char* pH = smc + SM_P + g * 14336;
        char* pL = pH + 7168;
        const uint32_t pHs = sb + SM_P + g * 14336;
        const uint32_t pLs = pHs + 7168;
        float* ls = reinterpret_cast<float*>(smc + SM_LSUM) + g * 32;
        const float* biasg = g_bias + g * (N_TOK * N_TOK);

        for (int grp = 0; grp < 4; grp++) {
            const int nmt  = (grp < 3) ? 2 : 1;
            const int mt0  = 2 * grp;
            const int row0 = 32 * grp;

            // ---- S = Q K^T: Q-frags hoisted per m-tile, nt split 4-way ----
            #pragma unroll 1
            for (int mt = mt0; mt < mt0 + nmt; mt++) {
                uint32_t qhf[2][4], qlf[2][4];
                #pragma unroll
                for (int ks = 0; ks < 2; ks++) {
                    int ao = sw_qk(mt * 16 + arow_l, ks * 16 + acol_l);
                    ldsm4(qhf[ks][0], qhf[ks][1], qhf[ks][2], qhf[ks][3], qhB + ao);
                    ldsm4(qlf[ks][0], qlf[ks][1], qlf[ks][2], qlf[ks][3], qlB + ao);
                }
                #pragma unroll 1
                for (int nt = subw; nt < 13; nt += 4) {
                    float acc[4] = {0.f, 0.f, 0.f, 0.f};
                    #pragma unroll
                    for (int ks = 0; ks < 2; ks++) {
                        uint32_t bhf[2], blf[2];
                        int bo = sw_qk(nt * 8 + (l15 & 7), ks * 16 + (l15 >> 3) * 8);
                        ldsm2(bhf[0], bhf[1], khB + bo);
                        ldsm2(blf[0], blf[1], klB + bo);
                        mma16816(acc, qhf[ks], bhf);
                        mma16816(acc, qhf[ks], blf);
                        mma16816(acc, qlf[ks], bhf);
                    }
                    int m0 = nt * 8 + kk_l;
                    #pragma unroll
                    for (int half = 0; half < 2; half++) {
                        int r = mt * 16 + nrow_l + half * 8;
                        float p0 = 0.f, p1 = 0.f;
                        if (r < N_TOK && m0 < N_TOK) {
                            float2 bv = __ldg(reinterpret_cast<const float2*>(
                                biasg + r * N_TOK + m0));
                            p0 = __expf(acc[2 * half + 0] + bv.x);
                            p1 = __expf(acc[2 * half + 1] + bv.y);
                        }
                        __nv_bfloat16 h0, l0, h1, l1;
                        split_bf16(p0, h0, l0);  split_bf16(p1, h1, l1);
                        int o = sw_p(r - row0, m0);
                        st_bf162(pH + o, h0, h1);
                        st_bf162(pL + o, l0, l1);
                    }
                }
            }
            asm volatile("bar.sync %0, %1;" :: "r"(g + 1), "r"(128) : "memory");

            // ---- PV: warp pinned to one m-group, ks-outer, per-nt accums ----
            float acc[3][4] = {{0.f,0.f,0.f,0.f},{0.f,0.f,0.f,0.f},{0.f,0.f,0.f,0.f}};
            int myn[3];
            int ncnt = 0;
            const int mtg   = (nmt == 2) ? (subw & 1) : 0;
            {
                int start = (nmt == 2) ? (subw >> 1) : subw;
                int step  = (nmt == 2) ? 2 : 4;
                for (int nt = start; nt < 5; nt += step) { myn[ncnt] = nt; ncnt++; }
            }
            #pragma unroll 1
            for (int ks = 0; ks < 7; ks++) {
                uint32_t ph4[4], pl4[4];
                int ao = sw_p(mtg * 16 + arow_l, ks * 16 + acol_l);
                ldsm4(ph4[0], ph4[1], ph4[2], ph4[3], pHs + ao);
                ldsm4(pl4[0], pl4[1], pl4[2], pl4[3], pLs + ao);
                #pragma unroll 1
                for (int j = 0; j < ncnt; j++) {
                    uint32_t bhf[2], blf[2];
                    uint32_t bo = (uint32_t)((ks * 16 + l15) * 40 + myn[j] * 8) * 2;
                    ldsm2t(bhf[0], bhf[1], vhB + bo);
                    ldsm2t(blf[0], blf[1], vlB + bo);
                    mma16816(acc[j], ph4, bhf);
                    mma16816(acc[j], ph4, blf);
                    mma16816(acc[j], pl4, bhf);
                }
            }
            for (int j = 0; j < ncnt; j++) {
                if (myn[j] == 4 && (lane & 3) == 0) {
                    int rg = mtg * 16 + nrow_l;
                    ls[rg]     = 1.0f / acc[j][0];
                    ls[rg + 8] = 1.0f / acc[j][2];
                }
            }
            asm volatile("bar.sync %0, %1;" :: "r"(g + 1), "r"(128) : "memory");

            // ---- scale by 1/rowsum -> A tiles (bf16 split) ----
            for (int j = 0; j < ncnt; j++) {
                if (myn[j] == 4) continue;
                int d0 = myn[j] * 8 + kk_l;
                #pragma unroll
                for (int half = 0; half < 2; half++) {
                    int rg = mtg * 16 + nrow_l + half * 8;
                    int r = row0 + rg;
                    if (r >= N_TOK) continue;
                    float inv = ls[rg];
                    float f0 = acc[j][2 * half + 0] * inv;
                    float f1 = acc[j][2 * half + 1] * inv;
                    __nv_bfloat16 h0, l0, h1, l1;
                    split_bf16(f0, h0, l0);  split_bf16(f1, h1, l1);
                    int off = swA(r, g * 32 + d0);
                    st_bf162(smc + SM_A_HI + off, h0, h1);
                    st_bf162(smc + SM_A_LO + off, l0, l1);
                }
            }
        }
    }
    __syncthreads();

    // ---- proj GEMM: warp = n-tile (12), 7 m-tiles; B-frags from gmem ----
    float* ost = reinterpret_cast<float*>(smc + SM_OST);
    {
        uint32_t bhf[6][2], blf[6][2];
        {
            int n = wid * 8 + nrow_l;
            const __nv_bfloat16* WH = g_wp_hi + n * 96;
            const __nv_bfloat16* WL = g_wp_lo + n * 96;
            #pragma unroll
            for (int ks = 0; ks < 6; ks++) {
                bhf[ks][0] = __ldg(reinterpret_cast<const uint32_t*>(WH + ks * 16 + kk_l));
                bhf[ks][1] = __ldg(reinterpret_cast<const uint32_t*>(WH + ks * 16 + kk_l + 8));
                blf[ks][0] = __ldg(reinterpret_cast<const uint32_t*>(WL + ks * 16 + kk_l));
                blf[ks][1] = __ldg(reinterpret_cast<const uint32_t*>(WL + ks * 16 + kk_l + 8));
            }
        }
        int colb = wid * 8 + kk_l;
        float b0 = __ldg(&proj_b[colb]);
        float b1 = __ldg(&proj_b[colb + 1]);
        for (int mt = 0; mt < 7; mt++) {
            float acc[4] = {0.f, 0.f, 0.f, 0.f};
            #pragma unroll
            for (int ksi = 0; ksi < 6; ksi++) {
                uint32_t offA = (uint32_t)swA(mt * 16 + arow_l, ksi * 16 + acol_l);
                uint32_t ah[4], al[4];
                ldsm4(ah[0], ah[1], ah[2], ah[3], sb + SM_A_HI + offA);
                ldsm4(al[0], al[1], al[2], al[3], sb + SM_A_LO + offA);
                mma16816(acc, ah, bhf[ksi]);
                mma16816(acc, ah, blf[ksi]);
                mma16816(acc, al, bhf[ksi]);
            }
            int r0 = mt * 16 + nrow_l;
            if (r0 < N_TOK) {
                float2 v; v.x = acc[0] + b0; v.y = acc[1] + b1;
                *reinterpret_cast<float2*>(ost + r0 * 100 + colb) = v;
            }
            int r1 = r0 + 8;
            if (r1 < N_TOK) {
                float2 v; v.x = acc[2] + b0; v.y = acc[3] + b1;
                *reinterpret_cast<float2*>(ost + r1 * 100 + colb) = v;
            }
        }
    }
    __syncthreads();

    // ---- coalesced final store ----
    {
        float4* og = reinterpret_cast<float4*>(out + base);
        for (int i = tid; i < N_TOK * (C_DIM / 4); i += NTHREADS) {
            int row = i / (C_DIM / 4), q = i - row * (C_DIM / 4);
            og[i] = *reinterpret_cast<const float4*>(ost + row * 100 + 4 * q);
        }
    }
}

// ---------------- launch ----------------
extern "C" void kernel_launch(void* const* d_in, const int* in_sizes, int n_in,
                              void* d_out, int out_size) {
    const float* x      = (const float*)d_in[0];
    const float* qkv_w  = (const float*)d_in[1];
    const float* qkv_b  = (const float*)d_in[2];
    const float* proj_w = (const float*)d_in[3];
    const float* proj_b = (const float*)d_in[4];
    const float* table  = (const float*)d_in[5];
    const int*   rel    = (const int*)d_in[6];
    float* out = (float*)d_out;

    cudaFuncSetAttribute(win_attn_mma,
                         cudaFuncAttributeMaxDynamicSharedMemorySize, SMEM_BYTES);

    int ntot = 288 * 96 + 96 * 96 + NHEAD * N_TOK * N_TOK;
    prep_all_kernel<<<(ntot + 255) / 256, 256>>>(qkv_w, proj_w, table, rel);
    win_attn_mma<<<4096, NTHREADS, SMEM_BYTES>>>(x, qkv_b, proj_b, out);
}

// round 17
// speedup vs baseline: 1.2737x; 1.2737x over previous
#include <cuda_runtime.h>
#include <cuda_bf16.h>
#include <cstdint>

// WindowAttention3D: B_=4096, N=98 tok, C=96, H=3 heads, hd=32.
// R17: R15 base + STATIC Q-fragment hoist in S phase + direct-gmem proj
// epilogue. (R16's dynamic-indexed variant regressed; this keeps the
// wavefront savings with fully static unrolling.)

#define N_TOK 98
#define C_DIM 96
#define NHEAD 3
#define NTHREADS 384

typedef unsigned long long u64;

// ---------------- helpers ----------------
__device__ __forceinline__ uint32_t smem_u32(const void* p) {
    uint32_t a;
    asm("{ .reg .u64 t; cvta.to.shared.u64 t, %1; cvt.u32.u64 %0, t; }"
        : "=r"(a) : "l"(p));
    return a;
}
__device__ __forceinline__ void ldsm4(uint32_t& r0, uint32_t& r1,
                                      uint32_t& r2, uint32_t& r3, uint32_t a) {
    asm volatile("ldmatrix.sync.aligned.m8n8.x4.shared.b16 {%0,%1,%2,%3}, [%4];"
                 : "=r"(r0), "=r"(r1), "=r"(r2), "=r"(r3) : "r"(a));
}
__device__ __forceinline__ void ldsm2(uint32_t& r0, uint32_t& r1, uint32_t a) {
    asm volatile("ldmatrix.sync.aligned.m8n8.x2.shared.b16 {%0,%1}, [%2];"
                 : "=r"(r0), "=r"(r1) : "r"(a));
}
__device__ __forceinline__ void ldsm2t(uint32_t& r0, uint32_t& r1, uint32_t a) {
    asm volatile("ldmatrix.sync.aligned.m8n8.x2.trans.shared.b16 {%0,%1}, [%2];"
                 : "=r"(r0), "=r"(r1) : "r"(a));
}
__device__ __forceinline__ void mma16816(float* c, const uint32_t* a,
                                         const uint32_t* b) {
    asm volatile("mma.sync.aligned.m16n8k16.row.col.f32.bf16.bf16.f32 "
                 "{%0,%1,%2,%3}, {%4,%5,%6,%7}, {%8,%9}, {%0,%1,%2,%3};"
                 : "+f"(c[0]), "+f"(c[1]), "+f"(c[2]), "+f"(c[3])
                 : "r"(a[0]), "r"(a[1]), "r"(a[2]), "r"(a[3]),
                   "r"(b[0]), "r"(b[1]));
}
__device__ __forceinline__ void split_bf16(float f, __nv_bfloat16& h, __nv_bfloat16& l) {
    h = __float2bfloat16(f);
    l = __float2bfloat16(f - __bfloat162float(h));
}
__device__ __forceinline__ void st_bf162(char* p, __nv_bfloat16 a, __nv_bfloat16 b) {
    __nv_bfloat162 t; t.x = a; t.y = b;
    *reinterpret_cast<__nv_bfloat162*>(p) = t;
}

// swizzled byte offsets (c = bf16 element column)
__device__ __forceinline__ int swA(int r, int c) {          // A: 192B rows
    return ((r * 96 + c) * 2) ^ (((r >> 1) & 3) << 4);
}
__device__ __forceinline__ int sw_qk(int r, int c) {        // q/k: 64B rows
    return (r * 64 + c * 2) ^ (((r >> 1) & 3) << 4);
}
__device__ __forceinline__ int sw_p(int r, int c) {         // P: 224B rows
    return (r * 224 + c * 2) ^ (((r >> 2) & 1) << 4);
}
// V: [m][40] bf16, 80B rows, no xor needed.

// ---------------- smem map (bytes) ----------------
constexpr int SM_A_HI = 0;                     // 112 x 192B
constexpr int SM_A_LO = 21504;
constexpr int SM_QH   = 43008;                 // + g*7168 (112 x 64B)
constexpr int SM_QL   = 64512;
constexpr int SM_KH   = 86016;                 // + g*6656 (104 x 64B)
constexpr int SM_KL   = 105984;
constexpr int SM_VH   = 125952;                // + g*8960 (112 x 80B)
constexpr int SM_VL   = 152832;
constexpr int SM_P    = 179712;                // + g*14336 (hi 7168 | lo 7168)
constexpr int SM_LSUM = 222720;                // 96 floats
constexpr int SMEM_BYTES = 223104;

// ---------------- device globals ----------------
__device__ float g_bias[NHEAD * N_TOK * N_TOK];        // [h][r][m]
__device__ __nv_bfloat16 g_wq_hi[288 * 96];            // row-major [n][k]
__device__ __nv_bfloat16 g_wq_lo[288 * 96];
__device__ __nv_bfloat16 g_wp_hi[96 * 96];
__device__ __nv_bfloat16 g_wp_lo[96 * 96];

__global__ void prep_all_kernel(const float* __restrict__ qkv_w,
                                const float* __restrict__ proj_w,
                                const float* __restrict__ table,
                                const int* __restrict__ rel) {
    int idx = blockIdx.x * blockDim.x + threadIdx.x;
    const int QE = 288 * 96, PE = 96 * 96;
    if (idx < QE) {
        float v = qkv_w[idx];
        __nv_bfloat16 hi, lo; split_bf16(v, hi, lo);
        g_wq_hi[idx] = hi;  g_wq_lo[idx] = lo;
    } else if (idx < QE + PE) {
        float v = proj_w[idx - QE];
        __nv_bfloat16 hi, lo; split_bf16(v, hi, lo);
        g_wp_hi[idx - QE] = hi;  g_wp_lo[idx - QE] = lo;
    } else if (idx < QE + PE + NHEAD * N_TOK * N_TOK) {
        int j = idx - QE - PE;
        int h   = j / (N_TOK * N_TOK);
        int rem = j - h * (N_TOK * N_TOK);
        int r   = rem / N_TOK;
        int m   = rem - r * N_TOK;
        g_bias[j] = table[rel[r * N_TOK + m] * NHEAD + h];
    }
}

// ---------------- main kernel ----------------
__global__ __launch_bounds__(NTHREADS, 1)
void win_attn_mma(const float* __restrict__ x,
                  const float* __restrict__ qkv_b,
                  const float* __restrict__ proj_b,
                  float* __restrict__ out) {
    extern __shared__ char smc[];
    const uint32_t sb = smem_u32(smc);
    const int tid  = threadIdx.x;
    const int wid  = tid >> 5;
    const int lane = tid & 31;
    const long base = (long)blockIdx.x * (N_TOK * C_DIM);

    const int arow_l = (lane & 7) + ((lane >> 3) & 1) * 8;
    const int acol_l = (lane >> 4) * 8;
    const int l15    = lane & 15;
    const int nrow_l = lane >> 2;          // B-frag n / C-frag row (0..7)
    const int kk_l   = (lane & 3) * 2;     // B-frag k / C-frag col pair

    // ---- zero V region; P pad cols; split x -> A hi/lo; ones col ----
    {
        uint4 z = {0, 0, 0, 0};
        uint4* vz = reinterpret_cast<uint4*>(smc + SM_VH);
        for (int i = tid; i < 2 * 3 * 8960 / 16; i += NTHREADS) vz[i] = z;
        for (int i = tid; i < 192; i += NTHREADS) {
            int g = i / 64, rb = i - g * 64;
            int bsel = rb >> 5, r = rb & 31;
            *reinterpret_cast<uint4*>(smc + SM_P + g * 14336 + bsel * 7168
                                      + sw_p(r, 104)) = z;
        }
    }
    for (int i = tid; i < N_TOK * (C_DIM / 2); i += NTHREADS) {
        int row = i / (C_DIM / 2), cp = i - row * (C_DIM / 2);
        float2 v = *reinterpret_cast<const float2*>(x + base + row * C_DIM + cp * 2);
        __nv_bfloat16 h0, l0, h1, l1;
        split_bf16(v.x, h0, l0);  split_bf16(v.y, h1, l1);
        int off = swA(row, cp * 2);
        st_bf162(smc + SM_A_HI + off, h0, h1);
        st_bf162(smc + SM_A_LO + off, l0, l1);
    }
    __syncthreads();
    for (int i = tid; i < NHEAD * N_TOK; i += NTHREADS) {
        int g = i / N_TOK, m = i - g * N_TOK;
        *reinterpret_cast<__nv_bfloat16*>(smc + SM_VH + g * 8960 + (m * 40 + 32) * 2) =
            __float2bfloat16(1.0f);
    }

    // ---- Phase B: QKV GEMM, 3 passes; B-frags direct from gmem ----
    const float scale = 0.17677669529663687f;   // 1/sqrt(32)
    const int ng = wid % 6;
    const int mg = wid / 6;
    const int m_begin = mg * 4;
    const int m_end   = (mg == 0) ? 4 : 7;

    #pragma unroll 1
    for (int s = 0; s < 3; s++) {
        uint32_t bh[2][6][2], bl[2][6][2];
        #pragma unroll
        for (int nt = 0; nt < 2; nt++) {
            int n = (2 * ng + nt) * 8 + nrow_l;
            const __nv_bfloat16* WH = g_wq_hi + (s * 96 + n) * 96;
            const __nv_bfloat16* WL = g_wq_lo + (s * 96 + n) * 96;
            #pragma unroll
            for (int ks = 0; ks < 6; ks++) {
                bh[nt][ks][0] = __ldg(reinterpret_cast<const uint32_t*>(WH + ks * 16 + kk_l));
                bh[nt][ks][1] = __ldg(reinterpret_cast<const uint32_t*>(WH + ks * 16 + kk_l + 8));
                bl[nt][ks][0] = __ldg(reinterpret_cast<const uint32_t*>(WL + ks * 16 + kk_l));
                bl[nt][ks][1] = __ldg(reinterpret_cast<const uint32_t*>(WL + ks * 16 + kk_l + 8));
            }
        }
        for (int mt = m_begin; mt < m_end; mt++) {
            float acc[2][4] = {{0.f, 0.f, 0.f, 0.f}, {0.f, 0.f, 0.f, 0.f}};
            #pragma unroll
            for (int ksi = 0; ksi < 6; ksi++) {
                uint32_t offA = (uint32_t)swA(mt * 16 + arow_l, ksi * 16 + acol_l);
                uint32_t ah[4], al[4];
                ldsm4(ah[0], ah[1], ah[2], ah[3], sb + SM_A_HI + offA);
                ldsm4(al[0], al[1], al[2], al[3], sb + SM_A_LO + offA);
                #pragma unroll
                for (int nt = 0; nt < 2; nt++) {
                    mma16816(acc[nt], ah, bh[nt][ksi]);
                    mma16816(acc[nt], ah, bl[nt][ksi]);
                    mma16816(acc[nt], al, bh[nt][ksi]);
                }
            }
            #pragma unroll
            for (int nt = 0; nt < 2; nt++) {
                int col = (2 * ng + nt) * 8 + kk_l;
                int hh = col >> 5, dd = col & 31;
                float b0 = __ldg(&qkv_b[s * C_DIM + col]);
                float b1 = __ldg(&qkv_b[s * C_DIM + col + 1]);
                float mul = (s == 0) ? scale : 1.0f;
                #pragma unroll
                for (int half = 0; half < 2; half++) {
                    int r = mt * 16 + nrow_l + half * 8;
                    if (r >= N_TOK) continue;
                    float f0 = (acc[nt][2 * half + 0] + b0) * mul;
                    float f1 = (acc[nt][2 * half + 1] + b1) * mul;
                    __nv_bfloat16 h0, l0, h1, l1;
                    split_bf16(f0, h0, l0);  split_bf16(f1, h1, l1);
                    if (s == 0) {
                        int o = sw_qk(r, dd);
                        st_bf162(smc + SM_QH + hh * 7168 + o, h0, h1);
                        st_bf162(smc + SM_QL + hh * 7168 + o, l0, l1);
                    } else if (s == 1) {
                        int o = sw_qk(r, dd);
                        st_bf162(smc + SM_KH + hh * 6656 + o, h0, h1);
                        st_bf162(smc + SM_KL + hh * 6656 + o, l0, l1);
                    } else {
                        int o = (r * 40 + dd) * 2;
                        st_bf162(smc + SM_VH + hh * 8960 + o, h0, h1);
                        st_bf162(smc + SM_VL + hh * 8960 + o, l0, l1);
                    }
                }
            }
        }
    }
    __syncthreads();

    // ---- Attention: 4 warps per head, named barriers, 4 row-groups ----
    {
        const int g    = wid >> 2;
        const int subw = wid & 3;
        const uint32_t qhB = sb + SM_QH + g * 7168;
        const uint32_t qlB = sb + SM_QL + g * 7168;
        const uint32_t khB = sb + SM_KH + g * 6656;
        const uint32_t klB = sb + SM_KL + g * 6656;
        const uint32_t vhB = sb + SM_VH + g * 8960;
        const uint32_t vlB = sb + SM_VL + g * 8960;
        char* pH = smc + SM_P + g * 14336;
        char* pL = pH + 7168;
        const uint32_t pHs = sb + SM_P + g * 14336;
        const uint32_t pLs = pHs + 7168;
        float* ls = reinterpret_cast<float*>(smc + SM_LSUM) + g * 32;
        const float* biasg = g_bias + g * (N_TOK * N_TOK);

        for (int grp = 0; grp < 4; grp++) {
            const int nmt  = (grp < 3) ? 2 : 1;
            const int mt0  = 2 * grp;
            const int row0 = 32 * grp;

            // ---- S = Q K^T: Q-frags hoisted per m-tile (STATIC inner loop) ----
            #pragma unroll 1
            for (int mt = mt0; mt < mt0 + nmt; mt++) {
                uint32_t qhf[2][4], qlf[2][4];
                #pragma unroll
                for (int ks = 0; ks < 2; ks++) {
                    int ao = sw_qk(mt * 16 + arow_l, ks * 16 + acol_l);
                    ldsm4(qhf[ks][0], qhf[ks][1], qhf[ks][2], qhf[ks][3], qhB + ao);
                    ldsm4(qlf[ks][0], qlf[ks][1], qlf[ks][2], qlf[ks][3], qlB + ao);
                }
                #pragma unroll
                for (int j = 0; j < 4; j++) {
                    int nt = subw + 4 * j;
                    if (nt < 13) {
                        float acc[4] = {0.f, 0.f, 0.f, 0.f};
                        #pragma unroll
                        for (int ks = 0; ks < 2; ks++) {
                            uint32_t bhf[2], blf[2];
                            int bo = sw_qk(nt * 8 + (l15 & 7), ks * 16 + (l15 >> 3) * 8);
                            ldsm2(bhf[0], bhf[1], khB + bo);
                            ldsm2(blf[0], blf[1], klB + bo);
                            mma16816(acc, qhf[ks], bhf);
                            mma16816(acc, qhf[ks], blf);
                            mma16816(acc, qlf[ks], bhf);
                        }
                        int m0 = nt * 8 + kk_l;
                        #pragma unroll
                        for (int half = 0; half < 2; half++) {
                            int r = mt * 16 + nrow_l + half * 8;
                            float p0 = 0.f, p1 = 0.f;
                            if (r < N_TOK && m0 < N_TOK) {
                                float2 bv = __ldg(reinterpret_cast<const float2*>(
                                    biasg + r * N_TOK + m0));
                                p0 = __expf(acc[2 * half + 0] + bv.x);
                                p1 = __expf(acc[2 * half + 1] + bv.y);
                            }
                            __nv_bfloat16 h0, l0, h1, l1;
                            split_bf16(p0, h0, l0);  split_bf16(p1, h1, l1);
                            int o = sw_p(r - row0, m0);
                            st_bf162(pH + o, h0, h1);
                            st_bf162(pL + o, l0, l1);
                        }
                    }
                }
            }
            asm volatile("bar.sync %0, %1;" :: "r"(g + 1), "r"(128) : "memory");

            // ---- PV (R15 form: V via ldmatrix.trans; nt=4 = ones -> rowsum) ----
            float pacc[3][4];
            int   ptile[3];
            int   np = 0;
            for (int t = subw; t < nmt * 5; t += 4) {
                int mtg = t / 5;
                int nt  = t % 5;
                float acc[4] = {0.f, 0.f, 0.f, 0.f};
                #pragma unroll
                for (int ks = 0; ks < 7; ks++) {
                    uint32_t ah[4], al[4], bhf[2], blf[2];
                    int ao = sw_p(mtg * 16 + arow_l, ks * 16 + acol_l);
                    ldsm4(ah[0], ah[1], ah[2], ah[3], pHs + ao);
                    ldsm4(al[0], al[1], al[2], al[3], pLs + ao);
                    uint32_t bo = (uint32_t)((ks * 16 + l15) * 40 + nt * 8) * 2;
                    ldsm2t(bhf[0], bhf[1], vhB + bo);
                    ldsm2t(blf[0], blf[1], vlB + bo);
                    mma16816(acc, ah, bhf);
                    mma16816(acc, ah, blf);
                    mma16816(acc, al, bhf);
                }
                if (nt == 4) {
                    if ((lane & 3) == 0) {
                        int rg = mtg * 16 + nrow_l;
                        ls[rg]     = 1.0f / acc[0];
                        ls[rg + 8] = 1.0f / acc[2];
                    }
                } else {
                    pacc[np][0] = acc[0]; pacc[np][1] = acc[1];
                    pacc[np][2] = acc[2]; pacc[np][3] = acc[3];
                    ptile[np] = t; np++;
                }
            }
            asm volatile("bar.sync %0, %1;" :: "r"(g + 1), "r"(128) : "memory");

            // ---- scale by 1/rowsum -> A tiles (bf16 split) ----
            for (int i = 0; i < np; i++) {
                int t = ptile[i];
                int mtg = t / 5, nt = t % 5;
                int d0 = nt * 8 + kk_l;
                #pragma unroll
                for (int half = 0; half < 2; half++) {
                    int rg = mtg * 16 + nrow_l + half * 8;
                    int r = row0 + rg;
                    if (r >= N_TOK) continue;
                    float inv = ls[rg];
                    float f0 = pacc[i][2 * half + 0] * inv;
                    float f1 = pacc[i][2 * half + 1] * inv;
                    __nv_bfloat16 h0, l0, h1, l1;
                    split_bf16(f0, h0, l0);  split_bf16(f1, h1, l1);
                    int off = swA(r, g * 32 + d0);
                    st_bf162(smc + SM_A_HI + off, h0, h1);
                    st_bf162(smc + SM_A_LO + off, l0, l1);
                }
            }
        }
    }
    __syncthreads();

    // ---- proj GEMM: warp = n-tile (12), 7 m-tiles; direct STG epilogue ----
    {
        uint32_t bhf[6][2], blf[6][2];
        {
            int n = wid * 8 + nrow_l;
            const __nv_bfloat16* WH = g_wp_hi + n * 96;
            const __nv_bfloat16* WL = g_wp_lo + n * 96;
            #pragma unroll
            for (int ks = 0; ks < 6; ks++) {
                bhf[ks][0] = __ldg(reinterpret_cast<const uint32_t*>(WH + ks * 16 + kk_l));
                bhf[ks][1] = __ldg(reinterpret_cast<const uint32_t*>(WH + ks * 16 + kk_l + 8));
                blf[ks][0] = __ldg(reinterpret_cast<const uint32_t*>(WL + ks * 16 + kk_l));
                blf[ks][1] = __ldg(reinterpret_cast<const uint32_t*>(WL + ks * 16 + kk_l + 8));
            }
        }
        int colb = wid * 8 + kk_l;
        float b0 = __ldg(&proj_b[colb]);
        float b1 = __ldg(&proj_b[colb + 1]);
        for (int mt = 0; mt < 7; mt++) {
            float acc[4] = {0.f, 0.f, 0.f, 0.f};
            #pragma unroll
            for (int ksi = 0; ksi < 6; ksi++) {
                uint32_t offA = (uint32_t)swA(mt * 16 + arow_l, ksi * 16 + acol_l);
                uint32_t ah[4], al[4];
                ldsm4(ah[0], ah[1], ah[2], ah[3], sb + SM_A_HI + offA);
                ldsm4(al[0], al[1], al[2], al[3], sb + SM_A_LO + offA);
                mma16816(acc, ah, bhf[ksi]);
                mma16816(acc, ah, blf[ksi]);
                mma16816(acc, al, bhf[ksi]);
            }
            int r0 = mt * 16 + nrow_l;
            if (r0 < N_TOK) {
                float2 v; v.x = acc[0] + b0; v.y = acc[1] + b1;
                *reinterpret_cast<float2*>(out + base + r0 * C_DIM + colb) = v;
            }
            int r1 = r0 + 8;
            if (r1 < N_TOK) {
                float2 v; v.x = acc[2] + b0; v.y = acc[3] + b1;
                *reinterpret_cast<float2*>(out + base + r1 * C_DIM + colb) = v;
            }
        }
    }
}

// ---------------- launch ----------------
extern "C" void kernel_launch(void* const* d_in, const int* in_sizes, int n_in,
                              void* d_out, int out_size) {
    const float* x      = (const float*)d_in[0];
    const float* qkv_w  = (const float*)d_in[1];
    const float* qkv_b  = (const float*)d_in[2];
    const float* proj_w = (const float*)d_in[3];
    const float* proj_b = (const float*)d_in[4];
    const float* table  = (const float*)d_in[5];
    const int*   rel    = (const int*)d_in[6];
    float* out = (float*)d_out;

    cudaFuncSetAttribute(win_attn_mma,
                         cudaFuncAttributeMaxDynamicSharedMemorySize, SMEM_BYTES);

    int ntot = 288 * 96 + 96 * 96 + NHEAD * N_TOK * N_TOK;
    prep_all_kernel<<<(ntot + 255) / 256, 256>>>(qkv_w, proj_w, table, rel);
    win_attn_mma<<<4096, NTHREADS, SMEM_BYTES>>>(x, qkv_b, proj_b, out);
}